// round 12
// baseline (speedup 1.0000x reference)
#include <cuda_runtime.h>
#include <cuda_fp16.h>
#include <stdint.h>
#include <math.h>

#define Bv 2
#define Sv 2048
#define Ev 2048
#define Hv 16
#define Dv 128
#define Mv (Bv*Sv)
#define Kv 2048

// ------------------------- device scratch -------------------------
__device__ __align__(256) __half g_xq[Mv*Kv];
__device__ __align__(256) __half g_xkv[Mv*Kv];
__device__ __align__(256) __half g_ctx[Mv*Kv];
__device__ __align__(256) __half g_w[4][Ev*Kv];
__device__ __align__(256) __half g_qh[Bv*Hv*Sv*Dv];  // Q: fp16, pre-scaled by log2e/sqrt(D)
__device__ __align__(256) __half g_kh[Bv*Hv*Sv*Dv];
__device__ __align__(256) __half g_vh[Bv*Hv*Sv*Dv];

// ------------------------- PTX helpers -------------------------
__device__ __forceinline__ uint32_t smem_u32(const void* p) {
    uint32_t a;
    asm("{ .reg .u64 t; cvta.to.shared.u64 t, %1; cvt.u32.u64 %0, t; }" : "=r"(a) : "l"(p));
    return a;
}
__device__ __forceinline__ void cp16(uint32_t dst, const void* src) {
    asm volatile("cp.async.cg.shared.global [%0], [%1], 16;" :: "r"(dst), "l"(src));
}
#define CP_COMMIT() asm volatile("cp.async.commit_group;" ::: "memory")
#define CP_WAIT(n)  asm volatile("cp.async.wait_group %0;" :: "n"(n) : "memory")

#define LDSM_X4(r, addr)                                                        \
    asm volatile("ldmatrix.sync.aligned.m8n8.x4.shared.b16 {%0,%1,%2,%3}, [%4];"\
        : "=r"((r)[0]), "=r"((r)[1]), "=r"((r)[2]), "=r"((r)[3]) : "r"(addr))

#define LDSM_X4_T(r, addr)                                                      \
    asm volatile("ldmatrix.sync.aligned.m8n8.x4.trans.shared.b16 {%0,%1,%2,%3}, [%4];"\
        : "=r"((r)[0]), "=r"((r)[1]), "=r"((r)[2]), "=r"((r)[3]) : "r"(addr))

#define MMA16816(c, a, b0, b1)                                                  \
    asm volatile("mma.sync.aligned.m16n8k16.row.col.f32.f16.f16.f32 "           \
        "{%0,%1,%2,%3}, {%4,%5,%6,%7}, {%8,%9}, {%0,%1,%2,%3};"                 \
        : "+f"((c)[0]), "+f"((c)[1]), "+f"((c)[2]), "+f"((c)[3])                 \
        : "r"((a)[0]), "r"((a)[1]), "r"((a)[2]), "r"((a)[3]), "r"(b0), "r"(b1))

__device__ __forceinline__ uint32_t h2_to_u32(__half a, __half b) {
    __half2 p = __halves2half2(a, b);
    return *(uint32_t*)&p;
}
__device__ __forceinline__ float fexp2(float x) {
    float r;
    asm("ex2.approx.ftz.f32 %0, %1;" : "=f"(r) : "f"(x));
    return r;
}

// ------------------------- convert fp32 -> fp16 -------------------------
__global__ __launch_bounds__(256) void convert_kernel(
    const float* __restrict__ in, __half* __restrict__ out, int n4)
{
    int i = blockIdx.x * blockDim.x + threadIdx.x;
    if (i >= n4) return;
    float4 x = ((const float4*)in)[i];
    ushort4 u;
    u.x = __half_as_ushort(__float2half_rn(x.x));
    u.y = __half_as_ushort(__float2half_rn(x.y));
    u.z = __half_as_ushort(__float2half_rn(x.z));
    u.w = __half_as_ushort(__float2half_rn(x.w));
    ((ushort4*)out)[i] = u;
}

// ------------------------- mma.sync GEMM (128x128 tile, BK=64, 2 CTAs/SM) ----
// C[m,n] = sum_k A[m,k]*W[n,k] + bias[n];  A, W single fp16.
// 8 warps = 2(M) x 4(N); warp tile 64x32.
// MODE 0: fp32 out [M,Ev]. MODE 3: fp16 out [B,H,S,D]. MODE 4: RoPE(*scl) + fp16 out.
#define BM 128
#define BN 128
#define BK 64
#define STAGES 3
#define NCHUNK (Kv / BK)      // 32
#define OFF_W  16384
#define STAGE_BYTES 32768
#define GEMM_SMEM 98304       // 3*32768; MODE4 staging 128*132*4=67584 fits

// swizzled byte offset of 16B chunk (row, ch) in a [rows][64] fp16 tile (128B rows)
__device__ __forceinline__ uint32_t swz64(int row, int ch) {
    return (uint32_t)(row * 128 + ((ch ^ (row & 7)) << 4));
}

template<int MODE>
__global__ __launch_bounds__(256, 2) void mma_gemm(
    const __half* __restrict__ A, const __half* __restrict__ W,
    const float* __restrict__ bias, float* __restrict__ C,
    __half* __restrict__ Chi,
    const float* __restrict__ cosb, const float* __restrict__ sinb, float scl)
{
    extern __shared__ __align__(1024) char smem[];
    const uint32_t sb = smem_u32(smem);
    const int tid = threadIdx.x, lane = tid & 31, wid = tid >> 5;
    const int warp_m = wid & 1, warp_n = wid >> 1;
    const int mBase = blockIdx.y * BM;
    const int colBase = blockIdx.x * BN;

    const int ldR = tid >> 1;           // 0..127
    const int ldC = (tid & 1) * 4;      // chunk 0..3 or 4..7

    auto load_chunk = [&](int c, int s) {
        const uint32_t base = sb + s * STAGE_BYTES;
        const size_t k0 = (size_t)c * BK + ldC * 8;
        const __half* a0 = A + (size_t)(mBase + ldR) * Kv + k0;
        const __half* w0 = W + (size_t)(colBase + ldR) * Kv + k0;
        #pragma unroll
        for (int j = 0; j < 4; j++) {
            cp16(base + swz64(ldR, ldC + j), a0 + j * 8);
            cp16(base + OFF_W + swz64(ldR, ldC + j), w0 + j * 8);
        }
        CP_COMMIT();
    };

    float acc[4][4][4];
    #pragma unroll
    for (int i = 0; i < 4; i++)
        #pragma unroll
        for (int j = 0; j < 4; j++)
            #pragma unroll
            for (int r = 0; r < 4; r++) acc[i][j][r] = 0.f;

    load_chunk(0, 0);
    load_chunk(1, 1);

    const int laneR = lane & 15, lc = lane >> 4;
    const int aRow = warp_m * 64 + laneR;
    const int bRow = warp_n * 32 + laneR;

    for (int c = 0; c < NCHUNK; c++) {
        CP_WAIT(1);
        __syncthreads();
        if (c + 2 < NCHUNK) load_chunk(c + 2, (c + 2) % 3);

        const uint32_t base = sb + (c % 3) * STAGE_BYTES;
        #pragma unroll
        for (int ks = 0; ks < 4; ks++) {
            const int c16 = ks * 2 + lc;
            uint32_t a4[4][4], b4[2][4];
            #pragma unroll
            for (int mi = 0; mi < 4; mi++)
                LDSM_X4(a4[mi], base + swz64(aRow + mi * 16, c16));
            #pragma unroll
            for (int nj = 0; nj < 2; nj++)
                LDSM_X4(b4[nj], base + OFF_W + swz64(bRow + nj * 16, c16));
            #pragma unroll
            for (int mi = 0; mi < 4; mi++)
                #pragma unroll
                for (int nt = 0; nt < 4; nt++)
                    MMA16816(acc[mi][nt], a4[mi],
                             b4[nt >> 1][nt & 1], b4[nt >> 1][2 + (nt & 1)]);
        }
    }

    const int g = lane >> 2, tig = lane & 3;
    const int h = colBase >> 7;          // BN=128 -> one head per block

    if (MODE == 0) {
        #pragma unroll
        for (int mi = 0; mi < 4; mi++) {
            const int r0 = mBase + warp_m * 64 + mi * 16 + g;
            const int r1 = r0 + 8;
            #pragma unroll
            for (int nt = 0; nt < 4; nt++) {
                const int col = colBase + warp_n * 32 + nt * 8 + tig * 2;
                const float2 bb = *(const float2*)&bias[col];
                float2 v0 = { acc[mi][nt][0] + bb.x, acc[mi][nt][1] + bb.y };
                float2 v1 = { acc[mi][nt][2] + bb.x, acc[mi][nt][3] + bb.y };
                *(float2*)&C[(size_t)r0 * Ev + col] = v0;
                *(float2*)&C[(size_t)r1 * Ev + col] = v1;
            }
        }
    } else if (MODE == 3) {
        #pragma unroll
        for (int mi = 0; mi < 4; mi++) {
            #pragma unroll
            for (int rr = 0; rr < 2; rr++) {
                const int m = mBase + warp_m * 64 + mi * 16 + g + rr * 8;
                const int bi = m >> 11, si = m & (Sv - 1);
                #pragma unroll
                for (int nt = 0; nt < 4; nt++) {
                    const int gcol = colBase + warp_n * 32 + nt * 8 + tig * 2;
                    const int d = gcol & 127;
                    const float2 bb = *(const float2*)&bias[gcol];
                    const float v0 = acc[mi][nt][rr*2+0] + bb.x;
                    const float v1 = acc[mi][nt][rr*2+1] + bb.y;
                    const size_t o = (((size_t)bi * Hv + h) * Sv + si) * Dv + d;
                    ushort2 uh = { __half_as_ushort(__float2half_rn(v0)),
                                   __half_as_ushort(__float2half_rn(v1)) };
                    *(ushort2*)&Chi[o] = uh;
                }
            }
        }
    } else {
        // MODE 4: RoPE(*scl) + fp16 out via smem staging ([128][132] fp32)
        __syncthreads();
        float* stg = (float*)smem;
        #pragma unroll
        for (int mi = 0; mi < 4; mi++) {
            const int r0 = warp_m * 64 + mi * 16 + g;
            #pragma unroll
            for (int nt = 0; nt < 4; nt++) {
                const int cidx = warp_n * 32 + nt * 8 + tig * 2;
                const float2 bb = *(const float2*)&bias[colBase + cidx];
                stg[(r0    ) * 132 + cidx    ] = acc[mi][nt][0] + bb.x;
                stg[(r0    ) * 132 + cidx + 1] = acc[mi][nt][1] + bb.y;
                stg[(r0 + 8) * 132 + cidx    ] = acc[mi][nt][2] + bb.x;
                stg[(r0 + 8) * 132 + cidx + 1] = acc[mi][nt][3] + bb.y;
            }
        }
        __syncthreads();
        #pragma unroll
        for (int t = 0; t < 32; t++) {
            const int idx = tid + t * 256;     // 128 rows * 64 d-pairs
            const int r = idx >> 6, d = idx & 63;
            const int m = mBase + r;
            const int bi = m >> 11, si = m & (Sv - 1);
            const float c1 = cosb[si*Dv + d],      s1 = sinb[si*Dv + d];
            const float c2 = cosb[si*Dv + d + 64], s2 = sinb[si*Dv + d + 64];
            const float x1 = stg[r * 132 + d];
            const float x2 = stg[r * 132 + d + 64];
            const float y1 = (x1 * c1 - x2 * s1) * scl;
            const float y2 = (x2 * c2 + x1 * s2) * scl;
            const size_t o = (((size_t)bi * Hv + h) * Sv + si) * Dv + d;
            Chi[o]      = __float2half_rn(y1);
            Chi[o + 64] = __float2half_rn(y2);
        }
    }
}

// ------------------------- flash attention, 1-sweep fp16, exp2 softmax -----------
// Q pre-scaled by log2(e)/sqrt(D): scores live in log2 domain, softmax uses ex2.
#define AT_Q 0
#define AT_STG 32768
#define AT_STGSZ 32768
#define AT_KH 0
#define AT_VH 16384
#define ATTN_SMEM 131072

__device__ __forceinline__ uint32_t swzA(int row, int ck) {
    return (uint32_t)(row * 256 + ((ck ^ (row & 7)) << 4));
}

__global__ __launch_bounds__(256, 1) void attn_mma(
    const __half* __restrict__ qh, const __half* __restrict__ kh,
    const __half* __restrict__ vh, __half* __restrict__ ch)
{
    extern __shared__ __align__(1024) char smem[];
    const uint32_t sb = smem_u32(smem);
    const int qb = (Sv/128 - 1) - blockIdx.x;
    const int h = blockIdx.y, b = blockIdx.z;
    const int tid = threadIdx.x, lane = tid & 31, wid = tid >> 5;

    const size_t headoff = (((size_t)b) * Hv + h) * Sv * Dv;
    const __half* Qg = qh + headoff + (size_t)qb * 128 * Dv;

    #pragma unroll
    for (int t = 0; t < 8; t++) {
        const int idx = tid + t * 256;
        const int r = idx >> 4, ck = idx & 15;
        cp16(sb + AT_Q + swzA(r, ck), Qg + (size_t)r * Dv + ck * 8);
    }
    CP_COMMIT();

    auto load_kv = [&](int kb2, int s) {
        const uint32_t base = sb + AT_STG + s * AT_STGSZ;
        const size_t off = headoff + (size_t)kb2 * 64 * Dv;
        #pragma unroll
        for (int t = 0; t < 4; t++) {
            const int idx = tid + t * 256;
            const int r = idx >> 4, ck = idx & 15;
            const uint32_t d = swzA(r, ck);
            const size_t go = off + (size_t)r * Dv + ck * 8;
            cp16(base + AT_KH + d, kh + go);
            cp16(base + AT_VH + d, vh + go);
        }
        CP_COMMIT();
    };

    const int nkb = 2 * qb + 2;
    load_kv(0, 0);
    if (nkb > 1) load_kv(1, 1);

    const int laneR = lane & 15, laneC = lane >> 4;
    const int g = lane >> 2, quadc = (lane & 3) * 2;
    const int rowbase = qb * 128 + wid * 16;

    CP_WAIT(2);
    __syncthreads();
    uint32_t qh_r[8][4];
    #pragma unroll
    for (int jj = 0; jj < 8; jj++)
        LDSM_X4(qh_r[jj], sb + AT_Q + swzA(wid * 16 + laneR, 2 * jj + laneC));

    float m_i[2] = {-1e30f, -1e30f};
    float l_i[2] = {0.f, 0.f};
    float O[16][4];
    #pragma unroll
    for (int t = 0; t < 16; t++)
        #pragma unroll
        for (int r = 0; r < 4; r++) O[t][r] = 0.f;

    for (int kb = 0; kb < nkb; kb++) {
        if (kb + 1 < nkb) CP_WAIT(1); else CP_WAIT(0);
        __syncthreads();
        if (kb + 2 < nkb) load_kv(kb + 2, (kb + 2) % 3);

        if (kb * 64 > rowbase + 15) continue;

        const uint32_t stg = sb + AT_STG + (kb % 3) * AT_STGSZ;

        float s[8][4];
        #pragma unroll
        for (int t = 0; t < 8; t++)
            #pragma unroll
            for (int r = 0; r < 4; r++) s[t][r] = 0.f;

        #pragma unroll
        for (int jj = 0; jj < 8; jj++) {
            const int ck = 2 * jj + laneC;
            uint32_t bh[4][4];
            #pragma unroll
            for (int t2 = 0; t2 < 4; t2++)
                LDSM_X4(bh[t2], stg + AT_KH + swzA(t2 * 16 + laneR, ck));
            #pragma unroll
            for (int t2 = 0; t2 < 4; t2++) {
                MMA16816(s[2*t2],   qh_r[jj], bh[t2][0], bh[t2][2]);
                MMA16816(s[2*t2+1], qh_r[jj], bh[t2][1], bh[t2][3]);
            }
        }

        if (kb * 64 + 63 > rowbase) {
            const int row0 = rowbase + g, row1 = row0 + 8;
            #pragma unroll
            for (int t = 0; t < 8; t++) {
                const int c0 = kb * 64 + t * 8 + quadc;
                if (c0     > row0) s[t][0] = -1e30f;
                if (c0 + 1 > row0) s[t][1] = -1e30f;
                if (c0     > row1) s[t][2] = -1e30f;
                if (c0 + 1 > row1) s[t][3] = -1e30f;
            }
        }

        float mx0 = -1e30f, mx1 = -1e30f;
        #pragma unroll
        for (int t = 0; t < 8; t++) {
            mx0 = fmaxf(mx0, fmaxf(s[t][0], s[t][1]));
            mx1 = fmaxf(mx1, fmaxf(s[t][2], s[t][3]));
        }
        mx0 = fmaxf(mx0, __shfl_xor_sync(0xffffffffu, mx0, 1));
        mx0 = fmaxf(mx0, __shfl_xor_sync(0xffffffffu, mx0, 2));
        mx1 = fmaxf(mx1, __shfl_xor_sync(0xffffffffu, mx1, 1));
        mx1 = fmaxf(mx1, __shfl_xor_sync(0xffffffffu, mx1, 2));
        const float mn0 = fmaxf(m_i[0], mx0);
        const float mn1 = fmaxf(m_i[1], mx1);
        const float al0 = fexp2(m_i[0] - mn0);
        const float al1 = fexp2(m_i[1] - mn1);
        m_i[0] = mn0; m_i[1] = mn1;
        float ps0 = 0.f, ps1 = 0.f;
        #pragma unroll
        for (int t = 0; t < 8; t++) {
            s[t][0] = fexp2(s[t][0] - mn0);
            s[t][1] = fexp2(s[t][1] - mn0);
            s[t][2] = fexp2(s[t][2] - mn1);
            s[t][3] = fexp2(s[t][3] - mn1);
            ps0 += s[t][0] + s[t][1];
            ps1 += s[t][2] + s[t][3];
        }
        ps0 += __shfl_xor_sync(0xffffffffu, ps0, 1);
        ps0 += __shfl_xor_sync(0xffffffffu, ps0, 2);
        ps1 += __shfl_xor_sync(0xffffffffu, ps1, 1);
        ps1 += __shfl_xor_sync(0xffffffffu, ps1, 2);
        l_i[0] = l_i[0] * al0 + ps0;
        l_i[1] = l_i[1] * al1 + ps1;
        #pragma unroll
        for (int t = 0; t < 16; t++) {
            O[t][0] *= al0; O[t][1] *= al0;
            O[t][2] *= al1; O[t][3] *= al1;
        }

        #pragma unroll
        for (int jj = 0; jj < 4; jj++) {
            uint32_t ah[4];
            #pragma unroll
            for (int q2 = 0; q2 < 2; q2++) {
                const int f = 2 * jj + q2;
                #pragma unroll
                for (int rr = 0; rr < 2; rr++) {
                    ah[q2 * 2 + rr] = h2_to_u32(__float2half_rn(s[f][rr*2+0]),
                                                __float2half_rn(s[f][rr*2+1]));
                }
            }
            #pragma unroll
            for (int t2 = 0; t2 < 8; t2++) {
                const int ck = 2 * t2 + laneC;
                uint32_t v4[4];
                LDSM_X4_T(v4, stg + AT_VH + swzA(jj * 16 + laneR, ck));
                MMA16816(O[2*t2],   ah, v4[0], v4[1]);
                MMA16816(O[2*t2+1], ah, v4[2], v4[3]);
            }
        }
    }

    const float inv0 = 1.f / l_i[0];
    const float inv1 = 1.f / l_i[1];
    const int row0 = rowbase + g;
    const size_t o0 = ((size_t)b * Sv + row0) * Ev + h * Dv;
    const size_t o1 = o0 + 8 * Ev;
    #pragma unroll
    for (int t = 0; t < 16; t++) {
        const int d = t * 8 + quadc;
        ushort2 uh0 = { __half_as_ushort(__float2half_rn(O[t][0] * inv0)),
                        __half_as_ushort(__float2half_rn(O[t][1] * inv0)) };
        ushort2 uh1 = { __half_as_ushort(__float2half_rn(O[t][2] * inv1)),
                        __half_as_ushort(__float2half_rn(O[t][3] * inv1)) };
        *(ushort2*)&ch[o0 + d] = uh0;
        *(ushort2*)&ch[o1 + d] = uh1;
    }
}

// ------------------------- launch -------------------------
extern "C" void kernel_launch(void* const* d_in, const int* in_sizes, int n_in,
                              void* d_out, int out_size)
{
    const float* x_q  = (const float*)d_in[0];
    const float* x_kv = (const float*)d_in[1];
    const float* cosb = (const float*)d_in[2];
    const float* sinb = (const float*)d_in[3];
    const float* wq   = (const float*)d_in[4];
    const float* bq   = (const float*)d_in[5];
    const float* wk   = (const float*)d_in[6];
    const float* bk   = (const float*)d_in[7];
    const float* wv   = (const float*)d_in[8];
    const float* bv   = (const float*)d_in[9];
    const float* wo   = (const float*)d_in[10];
    const float* bo   = (const float*)d_in[11];
    float* out = (float*)d_out;

    __half *xqp, *xkvp, *cxp, *wp, *qhp, *khp, *vhp;
    cudaGetSymbolAddress((void**)&xqp, g_xq);
    cudaGetSymbolAddress((void**)&xkvp, g_xkv);
    cudaGetSymbolAddress((void**)&cxp, g_ctx);
    cudaGetSymbolAddress((void**)&wp, g_w);
    cudaGetSymbolAddress((void**)&qhp, g_qh);
    cudaGetSymbolAddress((void**)&khp, g_kh);
    cudaGetSymbolAddress((void**)&vhp, g_vh);
    const size_t WSZ = (size_t)Ev * Kv;

    cudaFuncSetAttribute(mma_gemm<0>, cudaFuncAttributeMaxDynamicSharedMemorySize, GEMM_SMEM);
    cudaFuncSetAttribute(mma_gemm<3>, cudaFuncAttributeMaxDynamicSharedMemorySize, GEMM_SMEM);
    cudaFuncSetAttribute(mma_gemm<4>, cudaFuncAttributeMaxDynamicSharedMemorySize, GEMM_SMEM);
    cudaFuncSetAttribute(attn_mma, cudaFuncAttributeMaxDynamicSharedMemorySize, ATTN_SMEM);

    const int nx4 = Mv * Kv / 4;
    const int nw4 = Ev * Kv / 4;
    // 1/sqrt(128) * log2(e): scores come out of QK^T in log2 domain
    const float scl = 0.08838834764831845f * 1.4426950408889634f;
    dim3 gg(Ev/BN, Mv/BM);   // (16, 32) = 512 CTAs

    static cudaStream_t s1 = nullptr, s2 = nullptr;
    static cudaEvent_t eRoot = nullptr, eXKV = nullptr, eK = nullptr, eV = nullptr;
    if (s1 == nullptr) {
        cudaStreamCreateWithFlags(&s1, cudaStreamNonBlocking);
        cudaStreamCreateWithFlags(&s2, cudaStreamNonBlocking);
        cudaEventCreateWithFlags(&eRoot, cudaEventDisableTiming);
        cudaEventCreateWithFlags(&eXKV, cudaEventDisableTiming);
        cudaEventCreateWithFlags(&eK, cudaEventDisableTiming);
        cudaEventCreateWithFlags(&eV, cudaEventDisableTiming);
    }

    cudaEventRecord(eRoot, 0);
    cudaStreamWaitEvent(s1, eRoot, 0);
    cudaStreamWaitEvent(s2, eRoot, 0);

    // s0: Q path
    convert_kernel<<<nx4/256, 256>>>(x_q, xqp, nx4);
    convert_kernel<<<nw4/256, 256>>>(wq, wp + 0*WSZ, nw4);
    // s1: K path
    convert_kernel<<<nx4/256, 256, 0, s1>>>(x_kv, xkvp, nx4);
    cudaEventRecord(eXKV, s1);
    convert_kernel<<<nw4/256, 256, 0, s1>>>(wk, wp + 1*WSZ, nw4);
    // s2: V path
    cudaStreamWaitEvent(s2, eXKV, 0);
    convert_kernel<<<nw4/256, 256, 0, s2>>>(wv, wp + 2*WSZ, nw4);

    mma_gemm<4><<<gg, 256, GEMM_SMEM>>>(xqp, wp + 0*WSZ,
                                        bq, nullptr, qhp, cosb, sinb, scl);
    mma_gemm<4><<<gg, 256, GEMM_SMEM, s1>>>(xkvp, wp + 1*WSZ,
                                        bk, nullptr, khp, cosb, sinb, 1.0f);
    mma_gemm<3><<<gg, 256, GEMM_SMEM, s2>>>(xkvp, wp + 2*WSZ,
                                        bv, nullptr, vhp, nullptr, nullptr, 1.0f);

    convert_kernel<<<nw4/256, 256>>>(wo, wp + 3*WSZ, nw4);

    cudaEventRecord(eK, s1);
    cudaEventRecord(eV, s2);
    cudaStreamWaitEvent(0, eK, 0);
    cudaStreamWaitEvent(0, eV, 0);

    attn_mma<<<dim3(Sv/128, Hv, Bv), 256, ATTN_SMEM>>>(qhp, khp, vhp, cxp);

    mma_gemm<0><<<gg, 256, GEMM_SMEM>>>(cxp, wp + 3*WSZ,
                                        bo, out, nullptr, nullptr, nullptr, 1.0f);
}

// round 13
// speedup vs baseline: 1.0353x; 1.0353x over previous
#include <cuda_runtime.h>
#include <cuda_fp16.h>
#include <stdint.h>
#include <math.h>

#define Bv 2
#define Sv 2048
#define Ev 2048
#define Hv 16
#define Dv 128
#define Mv (Bv*Sv)
#define Kv 2048

// ------------------------- device scratch -------------------------
__device__ __align__(256) __half g_xq[Mv*Kv];
__device__ __align__(256) __half g_xkv[Mv*Kv];
__device__ __align__(256) __half g_ctx[Mv*Kv];
__device__ __align__(256) __half g_w[4][Ev*Kv];
__device__ __align__(256) __half g_qh[Bv*Hv*Sv*Dv];  // Q: fp16, pre-scaled by log2e/sqrt(D)
__device__ __align__(256) __half g_kh[Bv*Hv*Sv*Dv];
__device__ __align__(256) __half g_vh[Bv*Hv*Sv*Dv];

// ------------------------- PTX helpers -------------------------
__device__ __forceinline__ uint32_t smem_u32(const void* p) {
    uint32_t a;
    asm("{ .reg .u64 t; cvta.to.shared.u64 t, %1; cvt.u32.u64 %0, t; }" : "=r"(a) : "l"(p));
    return a;
}
__device__ __forceinline__ void cp16(uint32_t dst, const void* src) {
    asm volatile("cp.async.cg.shared.global [%0], [%1], 16;" :: "r"(dst), "l"(src));
}
#define CP_COMMIT() asm volatile("cp.async.commit_group;" ::: "memory")
#define CP_WAIT(n)  asm volatile("cp.async.wait_group %0;" :: "n"(n) : "memory")

#define LDSM_X4(r, addr)                                                        \
    asm volatile("ldmatrix.sync.aligned.m8n8.x4.shared.b16 {%0,%1,%2,%3}, [%4];"\
        : "=r"((r)[0]), "=r"((r)[1]), "=r"((r)[2]), "=r"((r)[3]) : "r"(addr))

#define LDSM_X4_T(r, addr)                                                      \
    asm volatile("ldmatrix.sync.aligned.m8n8.x4.trans.shared.b16 {%0,%1,%2,%3}, [%4];"\
        : "=r"((r)[0]), "=r"((r)[1]), "=r"((r)[2]), "=r"((r)[3]) : "r"(addr))

#define MMA16816(c, a, b0, b1)                                                  \
    asm volatile("mma.sync.aligned.m16n8k16.row.col.f32.f16.f16.f32 "           \
        "{%0,%1,%2,%3}, {%4,%5,%6,%7}, {%8,%9}, {%0,%1,%2,%3};"                 \
        : "+f"((c)[0]), "+f"((c)[1]), "+f"((c)[2]), "+f"((c)[3])                 \
        : "r"((a)[0]), "r"((a)[1]), "r"((a)[2]), "r"((a)[3]), "r"(b0), "r"(b1))

__device__ __forceinline__ uint32_t h2_to_u32(__half a, __half b) {
    __half2 p = __halves2half2(a, b);
    return *(uint32_t*)&p;
}
__device__ __forceinline__ float fexp2(float x) {
    float r;
    asm("ex2.approx.ftz.f32 %0, %1;" : "=f"(r) : "f"(x));
    return r;
}

// ------------------------- convert fp32 -> fp16 -------------------------
__global__ __launch_bounds__(256) void convert_kernel(
    const float* __restrict__ in, __half* __restrict__ out, int n4)
{
    int i = blockIdx.x * blockDim.x + threadIdx.x;
    if (i >= n4) return;
    float4 x = ((const float4*)in)[i];
    ushort4 u;
    u.x = __half_as_ushort(__float2half_rn(x.x));
    u.y = __half_as_ushort(__float2half_rn(x.y));
    u.z = __half_as_ushort(__float2half_rn(x.z));
    u.w = __half_as_ushort(__float2half_rn(x.w));
    ((ushort4*)out)[i] = u;
}

// ------------------------- mma.sync GEMM (128x256 tile, warp 64x64, 1-sweep fp16) ----
// (reverted to R11 shape: the 128x128/BK64 2-CTA variant regressed in R12)
// C[m,n] = sum_k A[m,k]*W[n,k] + bias[n];  A, W single fp16.
// MODE 0: fp32 out [M,Ev]. MODE 3: fp16 out [B,H,S,D]. MODE 4: RoPE(*scl) + fp16 out.
#define BM 128
#define BN 256
#define BK 32
#define STAGES 4
#define NCHUNK (Kv / BK)
#define OFF_W  8192
#define STAGE_BYTES 24576
#define GEMM_SMEM 135168   // max(4*24576, MODE4 staging 128*264*4)

__device__ __forceinline__ uint32_t swz(int row, int c) {
    const int blk = row >> 1;
    const int ch = ((row & 1) << 2) | c;
    return (uint32_t)(blk * 128 + ((ch ^ (blk & 7)) << 4));
}

template<int MODE>
__global__ __launch_bounds__(256, 1) void mma_gemm(
    const __half* __restrict__ A, const __half* __restrict__ W,
    const float* __restrict__ bias, float* __restrict__ C,
    __half* __restrict__ Chi,
    const float* __restrict__ cosb, const float* __restrict__ sinb, float scl)
{
    extern __shared__ __align__(1024) char smem[];
    const uint32_t sb = smem_u32(smem);
    const int tid = threadIdx.x, lane = tid & 31, wid = tid >> 5;
    const int warp_m = wid & 1, warp_n = wid >> 1;
    const int mBase = blockIdx.y * BM;
    const int colBase = blockIdx.x * BN;

    const int ldR = tid >> 2;
    const int ldC = tid & 3;
    const uint32_t swA0 = swz(ldR, ldC),       swA1 = swz(ldR + 64, ldC);
    const uint32_t swW0 = swz(ldR, ldC),       swW1 = swz(ldR + 64, ldC);
    const uint32_t swW2 = swz(ldR + 128, ldC), swW3 = swz(ldR + 192, ldC);

    auto load_chunk = [&](int c, int s) {
        const uint32_t base = sb + s * STAGE_BYTES;
        const size_t k0 = (size_t)c * BK + ldC * 8;
        const __half* a0 = A + (size_t)(mBase + ldR) * Kv + k0;
        cp16(base + swA0, a0);
        cp16(base + swA1, a0 + (size_t)64 * Kv);
        const __half* w0 = W + (size_t)(colBase + ldR) * Kv + k0;
        cp16(base + OFF_W + swW0, w0);
        cp16(base + OFF_W + swW1, w0 + (size_t)64 * Kv);
        cp16(base + OFF_W + swW2, w0 + (size_t)128 * Kv);
        cp16(base + OFF_W + swW3, w0 + (size_t)192 * Kv);
        CP_COMMIT();
    };

    float acc[4][8][4];
    #pragma unroll
    for (int i = 0; i < 4; i++)
        #pragma unroll
        for (int j = 0; j < 8; j++)
            #pragma unroll
            for (int r = 0; r < 4; r++) acc[i][j][r] = 0.f;

    load_chunk(0, 0);
    load_chunk(1, 1);
    load_chunk(2, 2);

    const int laneR = lane & 15, lc = lane >> 4;
    const int aRow = warp_m * 64 + laneR;
    const int bRow = warp_n * 64 + laneR;

    for (int c = 0; c < NCHUNK; c++) {
        CP_WAIT(2);
        __syncthreads();
        if (c + 3 < NCHUNK) load_chunk(c + 3, (c + 3) & 3);

        const uint32_t base = sb + (c & 3) * STAGE_BYTES;
        #pragma unroll
        for (int ks = 0; ks < 2; ks++) {
            const int c16 = ks * 2 + lc;
            uint32_t a4[4][4], b4[4][4];
            #pragma unroll
            for (int mi = 0; mi < 4; mi++)
                LDSM_X4(a4[mi], base + swz(aRow + mi * 16, c16));
            #pragma unroll
            for (int nj = 0; nj < 4; nj++)
                LDSM_X4(b4[nj], base + OFF_W + swz(bRow + nj * 16, c16));
            #pragma unroll
            for (int mi = 0; mi < 4; mi++)
                #pragma unroll
                for (int nj = 0; nj < 4; nj++) {
                    MMA16816(acc[mi][nj*2],   a4[mi], b4[nj][0], b4[nj][2]);
                    MMA16816(acc[mi][nj*2+1], a4[mi], b4[nj][1], b4[nj][3]);
                }
        }
    }

    const int g = lane >> 2, tig = lane & 3;

    if (MODE == 0) {
        #pragma unroll
        for (int mi = 0; mi < 4; mi++) {
            const int r0 = mBase + warp_m * 64 + mi * 16 + g;
            const int r1 = r0 + 8;
            #pragma unroll
            for (int nt = 0; nt < 8; nt++) {
                const int col = colBase + warp_n * 64 + nt * 8 + tig * 2;
                const float2 bb = *(const float2*)&bias[col];
                float2 v0 = { acc[mi][nt][0] + bb.x, acc[mi][nt][1] + bb.y };
                float2 v1 = { acc[mi][nt][2] + bb.x, acc[mi][nt][3] + bb.y };
                *(float2*)&C[(size_t)r0 * Ev + col] = v0;
                *(float2*)&C[(size_t)r1 * Ev + col] = v1;
            }
        }
    } else if (MODE == 3) {
        #pragma unroll
        for (int mi = 0; mi < 4; mi++) {
            #pragma unroll
            for (int rr = 0; rr < 2; rr++) {
                const int m = mBase + warp_m * 64 + mi * 16 + g + rr * 8;
                const int bi = m >> 11, si = m & (Sv - 1);
                #pragma unroll
                for (int nt = 0; nt < 8; nt++) {
                    const int gcol = colBase + warp_n * 64 + nt * 8 + tig * 2;
                    const int h = gcol >> 7, d = gcol & 127;
                    const float2 bb = *(const float2*)&bias[gcol];
                    const float v0 = acc[mi][nt][rr*2+0] + bb.x;
                    const float v1 = acc[mi][nt][rr*2+1] + bb.y;
                    const size_t o = (((size_t)bi * Hv + h) * Sv + si) * Dv + d;
                    ushort2 uh = { __half_as_ushort(__float2half_rn(v0)),
                                   __half_as_ushort(__float2half_rn(v1)) };
                    *(ushort2*)&Chi[o] = uh;
                }
            }
        }
    } else {
        // MODE 4: RoPE(*scl) + fp16 out via smem staging ([128][264] fp32)
        __syncthreads();
        float* stg = (float*)smem;
        #pragma unroll
        for (int mi = 0; mi < 4; mi++) {
            const int r0 = warp_m * 64 + mi * 16 + g;
            #pragma unroll
            for (int nt = 0; nt < 8; nt++) {
                const int cidx = warp_n * 64 + nt * 8 + tig * 2;
                const float2 bb = *(const float2*)&bias[colBase + cidx];
                stg[(r0    ) * 264 + cidx    ] = acc[mi][nt][0] + bb.x;
                stg[(r0    ) * 264 + cidx + 1] = acc[mi][nt][1] + bb.y;
                stg[(r0 + 8) * 264 + cidx    ] = acc[mi][nt][2] + bb.x;
                stg[(r0 + 8) * 264 + cidx + 1] = acc[mi][nt][3] + bb.y;
            }
        }
        __syncthreads();
        #pragma unroll
        for (int t = 0; t < 64; t++) {
            const int idx = tid + t * 256;
            const int r = idx >> 7;
            const int rem = idx & 127;
            const int hh = rem >> 6, d = rem & 63;
            const int m = mBase + r;
            const int bi = m >> 11, si = m & (Sv - 1);
            const float c1 = cosb[si*Dv + d],      s1 = sinb[si*Dv + d];
            const float c2 = cosb[si*Dv + d + 64], s2 = sinb[si*Dv + d + 64];
            const float x1 = stg[r * 264 + hh * 128 + d];
            const float x2 = stg[r * 264 + hh * 128 + d + 64];
            const float y1 = (x1 * c1 - x2 * s1) * scl;
            const float y2 = (x2 * c2 + x1 * s2) * scl;
            const int h = (colBase >> 7) + hh;
            const size_t o = (((size_t)bi * Hv + h) * Sv + si) * Dv + d;
            Chi[o]      = __float2half_rn(y1);
            Chi[o + 64] = __float2half_rn(y2);
        }
    }
}

// ------------------------- flash attention, 1-sweep fp16, exp2 softmax -----------
#define AT_Q 0
#define AT_STG 32768
#define AT_STGSZ 32768
#define AT_KH 0
#define AT_VH 16384
#define ATTN_SMEM 131072

__device__ __forceinline__ uint32_t swzA(int row, int ck) {
    return (uint32_t)(row * 256 + ((ck ^ (row & 7)) << 4));
}

__global__ __launch_bounds__(256, 1) void attn_mma(
    const __half* __restrict__ qh, const __half* __restrict__ kh,
    const __half* __restrict__ vh, __half* __restrict__ ch)
{
    extern __shared__ __align__(1024) char smem[];
    const uint32_t sb = smem_u32(smem);
    const int qb = (Sv/128 - 1) - blockIdx.x;
    const int h = blockIdx.y, b = blockIdx.z;
    const int tid = threadIdx.x, lane = tid & 31, wid = tid >> 5;

    const size_t headoff = (((size_t)b) * Hv + h) * Sv * Dv;
    const __half* Qg = qh + headoff + (size_t)qb * 128 * Dv;

    #pragma unroll
    for (int t = 0; t < 8; t++) {
        const int idx = tid + t * 256;
        const int r = idx >> 4, ck = idx & 15;
        cp16(sb + AT_Q + swzA(r, ck), Qg + (size_t)r * Dv + ck * 8);
    }
    CP_COMMIT();

    auto load_kv = [&](int kb2, int s) {
        const uint32_t base = sb + AT_STG + s * AT_STGSZ;
        const size_t off = headoff + (size_t)kb2 * 64 * Dv;
        #pragma unroll
        for (int t = 0; t < 4; t++) {
            const int idx = tid + t * 256;
            const int r = idx >> 4, ck = idx & 15;
            const uint32_t d = swzA(r, ck);
            const size_t go = off + (size_t)r * Dv + ck * 8;
            cp16(base + AT_KH + d, kh + go);
            cp16(base + AT_VH + d, vh + go);
        }
        CP_COMMIT();
    };

    const int nkb = 2 * qb + 2;
    load_kv(0, 0);
    if (nkb > 1) load_kv(1, 1);

    const int laneR = lane & 15, laneC = lane >> 4;
    const int g = lane >> 2, quadc = (lane & 3) * 2;
    const int rowbase = qb * 128 + wid * 16;

    CP_WAIT(2);
    __syncthreads();
    uint32_t qh_r[8][4];
    #pragma unroll
    for (int jj = 0; jj < 8; jj++)
        LDSM_X4(qh_r[jj], sb + AT_Q + swzA(wid * 16 + laneR, 2 * jj + laneC));

    float m_i[2] = {-1e30f, -1e30f};
    float l_i[2] = {0.f, 0.f};
    float O[16][4];
    #pragma unroll
    for (int t = 0; t < 16; t++)
        #pragma unroll
        for (int r = 0; r < 4; r++) O[t][r] = 0.f;

    for (int kb = 0; kb < nkb; kb++) {
        if (kb + 1 < nkb) CP_WAIT(1); else CP_WAIT(0);
        __syncthreads();
        if (kb + 2 < nkb) load_kv(kb + 2, (kb + 2) % 3);

        if (kb * 64 > rowbase + 15) continue;

        const uint32_t stg = sb + AT_STG + (kb % 3) * AT_STGSZ;

        float s[8][4];
        #pragma unroll
        for (int t = 0; t < 8; t++)
            #pragma unroll
            for (int r = 0; r < 4; r++) s[t][r] = 0.f;

        #pragma unroll
        for (int jj = 0; jj < 8; jj++) {
            const int ck = 2 * jj + laneC;
            uint32_t bh[4][4];
            #pragma unroll
            for (int t2 = 0; t2 < 4; t2++)
                LDSM_X4(bh[t2], stg + AT_KH + swzA(t2 * 16 + laneR, ck));
            #pragma unroll
            for (int t2 = 0; t2 < 4; t2++) {
                MMA16816(s[2*t2],   qh_r[jj], bh[t2][0], bh[t2][2]);
                MMA16816(s[2*t2+1], qh_r[jj], bh[t2][1], bh[t2][3]);
            }
        }

        if (kb * 64 + 63 > rowbase) {
            const int row0 = rowbase + g, row1 = row0 + 8;
            #pragma unroll
            for (int t = 0; t < 8; t++) {
                const int c0 = kb * 64 + t * 8 + quadc;
                if (c0     > row0) s[t][0] = -1e30f;
                if (c0 + 1 > row0) s[t][1] = -1e30f;
                if (c0     > row1) s[t][2] = -1e30f;
                if (c0 + 1 > row1) s[t][3] = -1e30f;
            }
        }

        float mx0 = -1e30f, mx1 = -1e30f;
        #pragma unroll
        for (int t = 0; t < 8; t++) {
            mx0 = fmaxf(mx0, fmaxf(s[t][0], s[t][1]));
            mx1 = fmaxf(mx1, fmaxf(s[t][2], s[t][3]));
        }
        mx0 = fmaxf(mx0, __shfl_xor_sync(0xffffffffu, mx0, 1));
        mx0 = fmaxf(mx0, __shfl_xor_sync(0xffffffffu, mx0, 2));
        mx1 = fmaxf(mx1, __shfl_xor_sync(0xffffffffu, mx1, 1));
        mx1 = fmaxf(mx1, __shfl_xor_sync(0xffffffffu, mx1, 2));
        const float mn0 = fmaxf(m_i[0], mx0);
        const float mn1 = fmaxf(m_i[1], mx1);
        const float al0 = fexp2(m_i[0] - mn0);
        const float al1 = fexp2(m_i[1] - mn1);
        m_i[0] = mn0; m_i[1] = mn1;
        float ps0 = 0.f, ps1 = 0.f;
        #pragma unroll
        for (int t = 0; t < 8; t++) {
            s[t][0] = fexp2(s[t][0] - mn0);
            s[t][1] = fexp2(s[t][1] - mn0);
            s[t][2] = fexp2(s[t][2] - mn1);
            s[t][3] = fexp2(s[t][3] - mn1);
            ps0 += s[t][0] + s[t][1];
            ps1 += s[t][2] + s[t][3];
        }
        ps0 += __shfl_xor_sync(0xffffffffu, ps0, 1);
        ps0 += __shfl_xor_sync(0xffffffffu, ps0, 2);
        ps1 += __shfl_xor_sync(0xffffffffu, ps1, 1);
        ps1 += __shfl_xor_sync(0xffffffffu, ps1, 2);
        l_i[0] = l_i[0] * al0 + ps0;
        l_i[1] = l_i[1] * al1 + ps1;
        #pragma unroll
        for (int t = 0; t < 16; t++) {
            O[t][0] *= al0; O[t][1] *= al0;
            O[t][2] *= al1; O[t][3] *= al1;
        }

        #pragma unroll
        for (int jj = 0; jj < 4; jj++) {
            uint32_t ah[4];
            #pragma unroll
            for (int q2 = 0; q2 < 2; q2++) {
                const int f = 2 * jj + q2;
                #pragma unroll
                for (int rr = 0; rr < 2; rr++) {
                    ah[q2 * 2 + rr] = h2_to_u32(__float2half_rn(s[f][rr*2+0]),
                                                __float2half_rn(s[f][rr*2+1]));
                }
            }
            #pragma unroll
            for (int t2 = 0; t2 < 8; t2++) {
                const int ck = 2 * t2 + laneC;
                uint32_t v4[4];
                LDSM_X4_T(v4, stg + AT_VH + swzA(jj * 16 + laneR, ck));
                MMA16816(O[2*t2],   ah, v4[0], v4[1]);
                MMA16816(O[2*t2+1], ah, v4[2], v4[3]);
            }
        }
    }

    const float inv0 = 1.f / l_i[0];
    const float inv1 = 1.f / l_i[1];
    const int row0 = rowbase + g;
    const size_t o0 = ((size_t)b * Sv + row0) * Ev + h * Dv;
    const size_t o1 = o0 + 8 * Ev;
    #pragma unroll
    for (int t = 0; t < 16; t++) {
        const int d = t * 8 + quadc;
        ushort2 uh0 = { __half_as_ushort(__float2half_rn(O[t][0] * inv0)),
                        __half_as_ushort(__float2half_rn(O[t][1] * inv0)) };
        ushort2 uh1 = { __half_as_ushort(__float2half_rn(O[t][2] * inv1)),
                        __half_as_ushort(__float2half_rn(O[t][3] * inv1)) };
        *(ushort2*)&ch[o0 + d] = uh0;
        *(ushort2*)&ch[o1 + d] = uh1;
    }
}

// ------------------------- launch -------------------------
extern "C" void kernel_launch(void* const* d_in, const int* in_sizes, int n_in,
                              void* d_out, int out_size)
{
    const float* x_q  = (const float*)d_in[0];
    const float* x_kv = (const float*)d_in[1];
    const float* cosb = (const float*)d_in[2];
    const float* sinb = (const float*)d_in[3];
    const float* wq   = (const float*)d_in[4];
    const float* bq   = (const float*)d_in[5];
    const float* wk   = (const float*)d_in[6];
    const float* bk   = (const float*)d_in[7];
    const float* wv   = (const float*)d_in[8];
    const float* bv   = (const float*)d_in[9];
    const float* wo   = (const float*)d_in[10];
    const float* bo   = (const float*)d_in[11];
    float* out = (float*)d_out;

    __half *xqp, *xkvp, *cxp, *wp, *qhp, *khp, *vhp;
    cudaGetSymbolAddress((void**)&xqp, g_xq);
    cudaGetSymbolAddress((void**)&xkvp, g_xkv);
    cudaGetSymbolAddress((void**)&cxp, g_ctx);
    cudaGetSymbolAddress((void**)&wp, g_w);
    cudaGetSymbolAddress((void**)&qhp, g_qh);
    cudaGetSymbolAddress((void**)&khp, g_kh);
    cudaGetSymbolAddress((void**)&vhp, g_vh);
    const size_t WSZ = (size_t)Ev * Kv;

    cudaFuncSetAttribute(mma_gemm<0>, cudaFuncAttributeMaxDynamicSharedMemorySize, GEMM_SMEM);
    cudaFuncSetAttribute(mma_gemm<3>, cudaFuncAttributeMaxDynamicSharedMemorySize, GEMM_SMEM);
    cudaFuncSetAttribute(mma_gemm<4>, cudaFuncAttributeMaxDynamicSharedMemorySize, GEMM_SMEM);
    cudaFuncSetAttribute(attn_mma, cudaFuncAttributeMaxDynamicSharedMemorySize, ATTN_SMEM);

    const int nx4 = Mv * Kv / 4;
    const int nw4 = Ev * Kv / 4;
    // 1/sqrt(128) * log2(e): scores come out of QK^T in log2 domain
    const float scl = 0.08838834764831845f * 1.4426950408889634f;
    dim3 gg(Ev/BN, Mv/BM);   // (8, 32)

    static cudaStream_t s1 = nullptr, s2 = nullptr;
    static cudaEvent_t eRoot = nullptr, eXKV = nullptr, eK = nullptr, eV = nullptr;
    if (s1 == nullptr) {
        cudaStreamCreateWithFlags(&s1, cudaStreamNonBlocking);
        cudaStreamCreateWithFlags(&s2, cudaStreamNonBlocking);
        cudaEventCreateWithFlags(&eRoot, cudaEventDisableTiming);
        cudaEventCreateWithFlags(&eXKV, cudaEventDisableTiming);
        cudaEventCreateWithFlags(&eK, cudaEventDisableTiming);
        cudaEventCreateWithFlags(&eV, cudaEventDisableTiming);
    }

    cudaEventRecord(eRoot, 0);
    cudaStreamWaitEvent(s1, eRoot, 0);
    cudaStreamWaitEvent(s2, eRoot, 0);

    // s0: Q path
    convert_kernel<<<nx4/256, 256>>>(x_q, xqp, nx4);
    convert_kernel<<<nw4/256, 256>>>(wq, wp + 0*WSZ, nw4);
    // s1: K path
    convert_kernel<<<nx4/256, 256, 0, s1>>>(x_kv, xkvp, nx4);
    cudaEventRecord(eXKV, s1);
    convert_kernel<<<nw4/256, 256, 0, s1>>>(wk, wp + 1*WSZ, nw4);
    // s2: V path
    cudaStreamWaitEvent(s2, eXKV, 0);
    convert_kernel<<<nw4/256, 256, 0, s2>>>(wv, wp + 2*WSZ, nw4);

    mma_gemm<4><<<gg, 256, GEMM_SMEM>>>(xqp, wp + 0*WSZ,
                                        bq, nullptr, qhp, cosb, sinb, scl);
    mma_gemm<4><<<gg, 256, GEMM_SMEM, s1>>>(xkvp, wp + 1*WSZ,
                                        bk, nullptr, khp, cosb, sinb, 1.0f);
    mma_gemm<3><<<gg, 256, GEMM_SMEM, s2>>>(xkvp, wp + 2*WSZ,
                                        bv, nullptr, vhp, nullptr, nullptr, 1.0f);

    convert_kernel<<<nw4/256, 256>>>(wo, wp + 3*WSZ, nw4);

    cudaEventRecord(eK, s1);
    cudaEventRecord(eV, s2);
    cudaStreamWaitEvent(0, eK, 0);
    cudaStreamWaitEvent(0, eV, 0);

    attn_mma<<<dim3(Sv/128, Hv, Bv), 256, ATTN_SMEM>>>(qhp, khp, vhp, cxp);

    mma_gemm<0><<<gg, 256, GEMM_SMEM>>>(cxp, wp + 3*WSZ,
                                        bo, out, nullptr, nullptr, nullptr, 1.0f);
}